// round 14
// baseline (speedup 1.0000x reference)
#include <cuda_runtime.h>
#include <cuda_bf16.h>
#include <cstdint>

// Problem constants (fixed by setup_inputs)
#define BATCH 64
#define CDIM  256
#define NPTS  1024
#define NQ    (BATCH * NPTS)
#define KOUT  9

// Scratch: d2 stored as full-precision order-preserving uint32 keys.
__device__ uint32_t g_d2[(size_t)BATCH * NPTS * NPTS];                     // 256MB
__device__ float g_sqp[8 * NQ];
__device__ float g_sq[NQ];
__device__ __align__(256) __nv_bfloat16 g_hi[(size_t)BATCH * NPTS * CDIM]; // 32MB [b][n][c]
__device__ __align__(256) __nv_bfloat16 g_lo[(size_t)BATCH * NPTS * CDIM]; // 32MB [b][n][c]

__device__ __forceinline__ uint32_t smem_u32(const void* p) {
    uint32_t a;
    asm("{ .reg .u64 t; cvta.to.shared.u64 t, %1; cvt.u32.u64 %0, t; }" : "=r"(a) : "l"(p));
    return a;
}
#define SW128(o) ((o) ^ (((o) >> 3) & 0x70))
#define FULL 0xffffffffu

__device__ __forceinline__ uint32_t fkey(float f) {
    uint32_t a = __float_as_uint(f);
    return a ^ (0x80000000u | (uint32_t)((int32_t)a >> 31));
}

// ---------------------------------------------------------------------------
// Kernel B: transpose + bf16 hi/lo split + fused partial squared norms.
// ---------------------------------------------------------------------------
__global__ void prep_kernel(const float* __restrict__ x) {
    __shared__ float T[32][33];
    int b  = blockIdx.z;
    int cb = blockIdx.y;
    int c0 = cb * 32;
    int n0 = blockIdx.x * 32;
    int tx = threadIdx.x, ty = threadIdx.y;   // (32, 8)
    const float* xb = x + (size_t)b * CDIM * NPTS;

    #pragma unroll
    for (int i = 0; i < 4; i++)
        T[ty + 8 * i][tx] = xb[(size_t)(c0 + ty + 8 * i) * NPTS + n0 + tx];
    __syncthreads();

    #pragma unroll
    for (int i = 0; i < 4; i++) {
        float v = T[tx][ty + 8 * i];
        __nv_bfloat16 hi = __float2bfloat16(v);
        __nv_bfloat16 lo = __float2bfloat16(v - __bfloat162float(hi));
        size_t o = ((size_t)(b * NPTS + n0 + ty + 8 * i) << 8) + c0 + tx;
        g_hi[o] = hi;
        g_lo[o] = lo;
        float s = v * v;
        #pragma unroll
        for (int off = 16; off > 0; off >>= 1)
            s += __shfl_xor_sync(FULL, s, off);
        if (tx == 0)
            g_sqp[cb * NQ + b * NPTS + n0 + ty + 8 * i] = s;
    }
}

__global__ void sqreduce_kernel() {
    int g = blockIdx.x * blockDim.x + threadIdx.x;
    float s = 0.0f;
    #pragma unroll
    for (int k = 0; k < 8; k++) s += g_sqp[k * NQ + g];
    g_sq[g] = s;
}

// ---------------------------------------------------------------------------
// Kernel C: mma.sync bf16 NT-GEMM -> fkey tokens (round-12 validated).
// ---------------------------------------------------------------------------
#define DYN_SMEM 66560

__device__ __forceinline__ void load_chunk(const __nv_bfloat16* A,
                                           const __nv_bfloat16* B,
                                           int m0, int n0, int k0,
                                           uint32_t sbase, int buf, int tid) {
    uint64_t ga, gb;
    asm("cvta.to.global.u64 %0, %1;" : "=l"(ga) : "l"(A));
    asm("cvta.to.global.u64 %0, %1;" : "=l"(gb) : "l"(B));
    uint32_t abase = sbase + buf * 16384;
    uint32_t bbase = sbase + 32768 + buf * 16384;
    #pragma unroll
    for (int i = 0; i < 4; i++) {
        int z = tid + (i << 8);
        int r = z >> 3, j = z & 7;
        uint64_t src = ga + (((size_t)(m0 + r) << 8) + k0 + j * 8) * 2;
        uint32_t dst = abase + SW128((uint32_t)(r * 128 + j * 16));
        asm volatile("cp.async.cg.shared.global [%0], [%1], 16;" :: "r"(dst), "l"(src));
    }
    #pragma unroll
    for (int i = 0; i < 4; i++) {
        int z = tid + (i << 8);
        int r = z >> 3, j = z & 7;
        uint64_t src = gb + (((size_t)(n0 + r) << 8) + k0 + j * 8) * 2;
        uint32_t dst = bbase + SW128((uint32_t)(r * 128 + j * 16));
        asm volatile("cp.async.cg.shared.global [%0], [%1], 16;" :: "r"(dst), "l"(src));
    }
    asm volatile("cp.async.commit_group;" ::: "memory");
}

__global__ void __launch_bounds__(256, 2) gemm_mma_kernel() {
    extern __shared__ char sm[];
    uint32_t sbase = smem_u32(sm);

    int tid = threadIdx.x;
    int wid = tid >> 5;
    int lane = tid & 31;
    int b = blockIdx.y;
    int p = blockIdx.x;
    int ti = 0, tj = 0;
    {
        int acc = 0;
        #pragma unroll
        for (int i = 0; i < 8; i++) {
            int cnt = 8 - i;
            if (p < acc + cnt) { ti = i; tj = i + (p - acc); break; }
            acc += cnt;
        }
    }
    int m0 = ti * 128, n0 = tj * 128;
    int wm = wid & 3, wn = wid >> 2;

    const __nv_bfloat16* hi = g_hi + ((size_t)b << 18);
    const __nv_bfloat16* lo = g_lo + ((size_t)b << 18);

    float c[2][8][4];
    #pragma unroll
    for (int mt = 0; mt < 2; mt++)
        #pragma unroll
        for (int j = 0; j < 8; j++)
            #pragma unroll
            for (int q = 0; q < 4; q++) c[mt][j][q] = 0.0f;

    int rowA = wm * 32 + (lane & 7) + (lane & 8);
    int kbA  = (lane & 16);
    int rowB = wn * 64 + (lane & 7) + ((lane & 16) >> 1);
    int kbB  = (lane & 8) << 1;

    auto term_ptrs = [&](int ch, const __nv_bfloat16*& A, const __nv_bfloat16*& B, int& k0) {
        int term = ch >> 2;
        k0 = (ch & 3) * 64;
        A = (term == 2) ? lo : hi;
        B = (term == 1) ? lo : hi;
    };

    {
        const __nv_bfloat16 *A, *B; int k0;
        term_ptrs(0, A, B, k0);
        load_chunk(A, B, m0, n0, k0, sbase, 0, tid);
    }

    for (int ch = 0; ch < 12; ch++) {
        if (ch + 1 < 12) {
            const __nv_bfloat16 *A, *B; int k0;
            term_ptrs(ch + 1, A, B, k0);
            load_chunk(A, B, m0, n0, k0, sbase, (ch + 1) & 1, tid);
            asm volatile("cp.async.wait_group 1;" ::: "memory");
        } else {
            asm volatile("cp.async.wait_group 0;" ::: "memory");
        }
        __syncthreads();

        int buf = ch & 1;
        uint32_t abase = sbase + buf * 16384;
        uint32_t bbase = sbase + 32768 + buf * 16384;

        #pragma unroll
        for (int kt = 0; kt < 4; kt++) {
            uint32_t a[2][4];
            #pragma unroll
            for (int mt = 0; mt < 2; mt++) {
                uint32_t addr = abase + SW128((uint32_t)((rowA + mt * 16) * 128 + kt * 32 + kbA));
                asm volatile("ldmatrix.sync.aligned.m8n8.x4.shared.b16 {%0,%1,%2,%3}, [%4];"
                             : "=r"(a[mt][0]), "=r"(a[mt][1]), "=r"(a[mt][2]), "=r"(a[mt][3])
                             : "r"(addr));
            }
            uint32_t bf[4][4];
            #pragma unroll
            for (int ng = 0; ng < 4; ng++) {
                uint32_t addr = bbase + SW128((uint32_t)((rowB + ng * 16) * 128 + kt * 32 + kbB));
                asm volatile("ldmatrix.sync.aligned.m8n8.x4.shared.b16 {%0,%1,%2,%3}, [%4];"
                             : "=r"(bf[ng][0]), "=r"(bf[ng][1]), "=r"(bf[ng][2]), "=r"(bf[ng][3])
                             : "r"(addr));
            }
            #pragma unroll
            for (int mt = 0; mt < 2; mt++)
                #pragma unroll
                for (int j = 0; j < 8; j++) {
                    uint32_t b0 = bf[j >> 1][(j & 1) * 2];
                    uint32_t b1 = bf[j >> 1][(j & 1) * 2 + 1];
                    asm volatile(
                        "mma.sync.aligned.m16n8k16.row.col.f32.bf16.bf16.f32 "
                        "{%0,%1,%2,%3}, {%4,%5,%6,%7}, {%8,%9}, {%0,%1,%2,%3};"
                        : "+f"(c[mt][j][0]), "+f"(c[mt][j][1]),
                          "+f"(c[mt][j][2]), "+f"(c[mt][j][3])
                        : "r"(a[mt][0]), "r"(a[mt][1]), "r"(a[mt][2]), "r"(a[mt][3]),
                          "r"(b0), "r"(b1));
                }
        }
        __syncthreads();
    }

    float* S = (float*)sm + wid * (32 * 65);
    int g = lane >> 2, t4 = lane & 3;
    #pragma unroll
    for (int mt = 0; mt < 2; mt++)
        #pragma unroll
        for (int j = 0; j < 8; j++) {
            int rr = mt * 16 + g, cc = j * 8 + t4 * 2;
            S[rr * 65 + cc]           = c[mt][j][0];
            S[rr * 65 + cc + 1]       = c[mt][j][1];
            S[(rr + 8) * 65 + cc]     = c[mt][j][2];
            S[(rr + 8) * 65 + cc + 1] = c[mt][j][3];
        }
    __syncwarp();

    const float* sqb = g_sq + (b << 10);
    uint32_t* dbase = g_d2 + ((size_t)b << 20);
    int mg = m0 + wm * 32, ng = n0 + wn * 64;

    float sqc0 = sqb[ng + 2 * lane];
    float sqc1 = sqb[ng + 2 * lane + 1];
    #pragma unroll 4
    for (int r = 0; r < 32; r++) {
        float sq_m = sqb[mg + r];
        uint32_t* drow = dbase + (size_t)(mg + r) * NPTS + ng;
        uint2 v;
        v.x = fkey(sq_m + sqc0 - 2.0f * S[r * 65 + 2 * lane]);
        v.y = fkey(sq_m + sqc1 - 2.0f * S[r * 65 + 2 * lane + 1]);
        *(uint2*)(drow + 2 * lane) = v;
    }

    if (ti != tj) {
        float sq_ml = sqb[mg + lane];
        #pragma unroll 4
        for (int cix = 0; cix < 64; cix++) {
            float sq_n = sqb[ng + cix];
            dbase[(size_t)(ng + cix) * NPTS + mg + lane] =
                fkey(sq_n + sq_ml - 2.0f * S[lane * 65 + cix]);
        }
    }
}

// ---------------------------------------------------------------------------
// Kernel D: selection with 32-bit sort + exact index recovery.
// Lane owns keys m in [lane*32, lane*32+32) -> compaction buffer is monotone
// in m; equal keys resolve ascending-m via ballot/__fns counting (exact JAX).
// ---------------------------------------------------------------------------
__global__ void __launch_bounds__(256, 4) select_knn_kernel(
        const int* __restrict__ layer_idx, float* __restrict__ out, int half) {
    __shared__ uint32_t kbuf[8][64];
    __shared__ uint32_t mbuf[8][64];

    int blk = gridDim.x - 1 - blockIdx.x;          // reversed scheduling
    int warp = blk * 8 + (threadIdx.x >> 5);
    int lane = threadIdx.x & 31;
    int w = (threadIdx.x >> 5);
    if (warp >= NQ) return;

    int li = layer_idx[0];
    int dil = li / 4 + 1;
    if (dil > 3) dil = 3;
    if (dil < 1) dil = 1;

    const uint32_t* row = g_d2 + ((size_t)warp << 10);

    // lane owns m = lane*32 + s  (contiguous 128B per lane; row is L1-hot)
    uint32_t u[32];
    #pragma unroll
    for (int i = 0; i < 8; i++) {
        uint4 t = *(const uint4*)(row + lane * 32 + i * 4);
        u[i * 4 + 0] = t.x; u[i * 4 + 1] = t.y;
        u[i * 4 + 2] = t.z; u[i * 4 + 3] = t.w;
    }

    uint32_t lmin = u[0];
    #pragma unroll
    for (int s = 1; s < 32; s++) lmin = min(lmin, u[s]);

    uint32_t sv = lmin;
    #pragma unroll
    for (int k = 2; k <= 32; k <<= 1) {
        #pragma unroll
        for (int j = k >> 1; j > 0; j >>= 1) {
            uint32_t o = __shfl_xor_sync(FULL, sv, j);
            bool up = ((lane & k) == 0) || (k == 32);
            bool lower = ((lane & j) == 0);
            uint32_t mn = min(sv, o), mx = max(sv, o);
            sv = (up == lower) ? mn : mx;
        }
    }
    uint32_t T = __shfl_sync(FULL, sv, 24);

    int cnt = 0;
    #pragma unroll
    for (int s = 0; s < 32; s++) cnt += (u[s] <= T);
    int inc = cnt;
    #pragma unroll
    for (int j = 1; j < 32; j <<= 1) {
        int n = __shfl_up_sync(FULL, inc, j);
        if (lane >= j) inc += n;
    }
    int excl = inc - cnt;
    int C = __shfl_sync(FULL, inc, 31);

    int b = warp >> 10;
    int outbase = warp * KOUT;

    if (C <= 64) {
        // compaction: buffer monotone in m (lane-major, s ascending)
        int pos = excl;
        #pragma unroll
        for (int s = 0; s < 32; s++) {
            if (u[s] <= T) {
                kbuf[w][pos] = u[s];
                mbuf[w][pos] = (uint32_t)(lane * 32 + s);
                pos++;
            }
        }
        __syncwarp();

        uint32_t y0 = (lane < C)      ? kbuf[w][lane]      : 0xFFFFFFFFu;
        uint32_t y1 = (lane + 32 < C) ? kbuf[w][lane + 32] : 0xFFFFFFFFu;
        uint32_t x0 = y0, x1 = y1;

        // bitonic sort of 64 keys (32-bit)
        #pragma unroll
        for (int k = 2; k <= 64; k <<= 1) {
            #pragma unroll
            for (int j = k >> 1; j > 0; j >>= 1) {
                if (j == 32) {
                    uint32_t mn = min(x0, x1), mx = max(x0, x1);
                    x0 = mn; x1 = mx;
                } else {
                    bool lower = ((lane & j) == 0);
                    bool up0, up1;
                    if (k == 64)      { up0 = true;  up1 = true;  }
                    else if (k == 32) { up0 = true;  up1 = false; }
                    else { up0 = up1 = ((lane & k) == 0); }
                    uint32_t o0 = __shfl_xor_sync(FULL, x0, j);
                    uint32_t o1 = __shfl_xor_sync(FULL, x1, j);
                    x0 = (up0 == lower) ? min(x0, o0) : max(x0, o0);
                    x1 = (up1 == lower) ? min(x1, o1) : max(x1, o1);
                }
            }
        }

        // exact rank -> index recovery (ties ascending-m via monotone buffer)
        for (int t = 0; t <= 8; t++) {
            int rank = t * dil;
            uint32_t K = __shfl_sync(FULL, x0, rank);
            uint32_t eqs = __ballot_sync(FULL, x0 == K);
            int tlt = __popc(eqs & ((rank > 0) ? ((1u << rank) - 1u) : 0u));
            uint32_t b0m = __ballot_sync(FULL, y0 == K);
            uint32_t b1m = __ballot_sync(FULL, y1 == K);
            if (lane == 0) {
                int c0m = __popc(b0m);
                int p2 = (tlt < c0m) ? (int)__fns(b0m, 0, tlt + 1)
                                     : 32 + (int)__fns(b1m, 0, tlt - c0m + 1);
                int m = (int)mbuf[w][p2];
                int oi = outbase + t;
                out[oi] = (float)((b << 10) + m);
                out[half + oi] = (float)warp;
            }
        }
    } else {
        // rare fallback: exact extract-min on (key, m)
        uint32_t bv = u[0];
        int bs = 0;
        #pragma unroll
        for (int s = 1; s < 32; s++)
            if (u[s] < bv) { bv = u[s]; bs = s; }

        int iters = 8 * dil + 1;
        for (int r = 0; r < iters; r++) {
            uint32_t wv = bv;
            int wmm = lane * 32 + bs;
            #pragma unroll
            for (int o = 16; o > 0; o >>= 1) {
                uint32_t ov = __shfl_xor_sync(FULL, wv, o);
                int om = __shfl_xor_sync(FULL, wmm, o);
                if (ov < wv || (ov == wv && om < wmm)) { wv = ov; wmm = om; }
            }
            if ((r % dil) == 0 && lane == 0) {
                int oi = outbase + r / dil;
                out[oi] = (float)((b << 10) + wmm);
                out[half + oi] = (float)warp;
            }
            int owner = wmm >> 5;
            if (lane == owner) {
                int s = wmm & 31;
                #pragma unroll
                for (int ss = 0; ss < 32; ss++)
                    if (ss == s) u[ss] = 0xFFFFFFFFu;
                bv = u[0]; bs = 0;
                #pragma unroll
                for (int ss = 1; ss < 32; ss++)
                    if (u[ss] < bv) { bv = u[ss]; bs = ss; }
            }
        }
    }
}

// ---------------------------------------------------------------------------
// Launch — inputs identified BY SIZE (x = 16,777,216 elems; layer_idx = 1)
// ---------------------------------------------------------------------------
extern "C" void kernel_launch(void* const* d_in, const int* in_sizes, int n_in,
                              void* d_out, int out_size) {
    int xi = 0, li = 1;
    if (n_in >= 2) {
        if (in_sizes[0] >= in_sizes[1]) { xi = 0; li = 1; }
        else                            { xi = 1; li = 0; }
    } else { xi = 0; li = 0; }

    const float* x = (const float*)d_in[xi];
    const int* layer_idx = (const int*)d_in[li];
    float* out = (float*)d_out;
    int half = out_size / 2;

    cudaFuncSetAttribute(gemm_mma_kernel,
                         cudaFuncAttributeMaxDynamicSharedMemorySize, DYN_SMEM);

    dim3 pg(32, 8, 64);
    prep_kernel<<<pg, dim3(32, 8)>>>(x);

    sqreduce_kernel<<<NQ / 256, 256>>>();

    dim3 gg(36, BATCH);
    gemm_mma_kernel<<<gg, 256, DYN_SMEM>>>();

    select_knn_kernel<<<NQ / 8, 256>>>(layer_idx, out, half);
}

// round 15
// speedup vs baseline: 1.1324x; 1.1324x over previous
#include <cuda_runtime.h>
#include <cuda_bf16.h>
#include <cstdint>

// Problem constants (fixed by setup_inputs)
#define BATCH 64
#define CDIM  256
#define NPTS  1024
#define NQ    (BATCH * NPTS)
#define KOUT  9

// Scratch: d2 stored as full-precision order-preserving uint32 keys.
__device__ uint32_t g_d2[(size_t)BATCH * NPTS * NPTS];                     // 256MB
__device__ float g_sqp[8 * NQ];
__device__ float g_sq[NQ];
__device__ __align__(256) __nv_bfloat16 g_hi[(size_t)BATCH * NPTS * CDIM]; // 32MB [b][n][c]
__device__ __align__(256) __nv_bfloat16 g_lo[(size_t)BATCH * NPTS * CDIM]; // 32MB [b][n][c]

__device__ __forceinline__ uint32_t smem_u32(const void* p) {
    uint32_t a;
    asm("{ .reg .u64 t; cvta.to.shared.u64 t, %1; cvt.u32.u64 %0, t; }" : "=r"(a) : "l"(p));
    return a;
}
#define SW128(o) ((o) ^ (((o) >> 3) & 0x70))
#define FULL 0xffffffffu

__device__ __forceinline__ uint32_t fkey(float f) {
    uint32_t a = __float_as_uint(f);
    return a ^ (0x80000000u | (uint32_t)((int32_t)a >> 31));
}

// ---------------------------------------------------------------------------
// Kernel B: transpose + bf16 hi/lo split + fused partial squared norms.
// ---------------------------------------------------------------------------
__global__ void prep_kernel(const float* __restrict__ x) {
    __shared__ float T[32][33];
    int b  = blockIdx.z;
    int cb = blockIdx.y;
    int c0 = cb * 32;
    int n0 = blockIdx.x * 32;
    int tx = threadIdx.x, ty = threadIdx.y;   // (32, 8)
    const float* xb = x + (size_t)b * CDIM * NPTS;

    #pragma unroll
    for (int i = 0; i < 4; i++)
        T[ty + 8 * i][tx] = xb[(size_t)(c0 + ty + 8 * i) * NPTS + n0 + tx];
    __syncthreads();

    #pragma unroll
    for (int i = 0; i < 4; i++) {
        float v = T[tx][ty + 8 * i];
        __nv_bfloat16 hi = __float2bfloat16(v);
        __nv_bfloat16 lo = __float2bfloat16(v - __bfloat162float(hi));
        size_t o = ((size_t)(b * NPTS + n0 + ty + 8 * i) << 8) + c0 + tx;
        g_hi[o] = hi;
        g_lo[o] = lo;
        float s = v * v;
        #pragma unroll
        for (int off = 16; off > 0; off >>= 1)
            s += __shfl_xor_sync(FULL, s, off);
        if (tx == 0)
            g_sqp[cb * NQ + b * NPTS + n0 + ty + 8 * i] = s;
    }
}

__global__ void sqreduce_kernel() {
    int g = blockIdx.x * blockDim.x + threadIdx.x;
    float s = 0.0f;
    #pragma unroll
    for (int k = 0; k < 8; k++) s += g_sqp[k * NQ + g];
    g_sq[g] = s;
}

// ---------------------------------------------------------------------------
// Kernel C: mma.sync bf16 NT-GEMM -> fkey tokens (round-12 validated).
// ---------------------------------------------------------------------------
#define DYN_SMEM 66560

__device__ __forceinline__ void load_chunk(const __nv_bfloat16* A,
                                           const __nv_bfloat16* B,
                                           int m0, int n0, int k0,
                                           uint32_t sbase, int buf, int tid) {
    uint64_t ga, gb;
    asm("cvta.to.global.u64 %0, %1;" : "=l"(ga) : "l"(A));
    asm("cvta.to.global.u64 %0, %1;" : "=l"(gb) : "l"(B));
    uint32_t abase = sbase + buf * 16384;
    uint32_t bbase = sbase + 32768 + buf * 16384;
    #pragma unroll
    for (int i = 0; i < 4; i++) {
        int z = tid + (i << 8);
        int r = z >> 3, j = z & 7;
        uint64_t src = ga + (((size_t)(m0 + r) << 8) + k0 + j * 8) * 2;
        uint32_t dst = abase + SW128((uint32_t)(r * 128 + j * 16));
        asm volatile("cp.async.cg.shared.global [%0], [%1], 16;" :: "r"(dst), "l"(src));
    }
    #pragma unroll
    for (int i = 0; i < 4; i++) {
        int z = tid + (i << 8);
        int r = z >> 3, j = z & 7;
        uint64_t src = gb + (((size_t)(n0 + r) << 8) + k0 + j * 8) * 2;
        uint32_t dst = bbase + SW128((uint32_t)(r * 128 + j * 16));
        asm volatile("cp.async.cg.shared.global [%0], [%1], 16;" :: "r"(dst), "l"(src));
    }
    asm volatile("cp.async.commit_group;" ::: "memory");
}

__global__ void __launch_bounds__(256, 2) gemm_mma_kernel() {
    extern __shared__ char sm[];
    uint32_t sbase = smem_u32(sm);

    int tid = threadIdx.x;
    int wid = tid >> 5;
    int lane = tid & 31;
    int b = blockIdx.y;
    int p = blockIdx.x;
    int ti = 0, tj = 0;
    {
        int acc = 0;
        #pragma unroll
        for (int i = 0; i < 8; i++) {
            int cnt = 8 - i;
            if (p < acc + cnt) { ti = i; tj = i + (p - acc); break; }
            acc += cnt;
        }
    }
    int m0 = ti * 128, n0 = tj * 128;
    int wm = wid & 3, wn = wid >> 2;

    const __nv_bfloat16* hi = g_hi + ((size_t)b << 18);
    const __nv_bfloat16* lo = g_lo + ((size_t)b << 18);

    float c[2][8][4];
    #pragma unroll
    for (int mt = 0; mt < 2; mt++)
        #pragma unroll
        for (int j = 0; j < 8; j++)
            #pragma unroll
            for (int q = 0; q < 4; q++) c[mt][j][q] = 0.0f;

    int rowA = wm * 32 + (lane & 7) + (lane & 8);
    int kbA  = (lane & 16);
    int rowB = wn * 64 + (lane & 7) + ((lane & 16) >> 1);
    int kbB  = (lane & 8) << 1;

    auto term_ptrs = [&](int ch, const __nv_bfloat16*& A, const __nv_bfloat16*& B, int& k0) {
        int term = ch >> 2;
        k0 = (ch & 3) * 64;
        A = (term == 2) ? lo : hi;
        B = (term == 1) ? lo : hi;
    };

    {
        const __nv_bfloat16 *A, *B; int k0;
        term_ptrs(0, A, B, k0);
        load_chunk(A, B, m0, n0, k0, sbase, 0, tid);
    }

    for (int ch = 0; ch < 12; ch++) {
        if (ch + 1 < 12) {
            const __nv_bfloat16 *A, *B; int k0;
            term_ptrs(ch + 1, A, B, k0);
            load_chunk(A, B, m0, n0, k0, sbase, (ch + 1) & 1, tid);
            asm volatile("cp.async.wait_group 1;" ::: "memory");
        } else {
            asm volatile("cp.async.wait_group 0;" ::: "memory");
        }
        __syncthreads();

        int buf = ch & 1;
        uint32_t abase = sbase + buf * 16384;
        uint32_t bbase = sbase + 32768 + buf * 16384;

        #pragma unroll
        for (int kt = 0; kt < 4; kt++) {
            uint32_t a[2][4];
            #pragma unroll
            for (int mt = 0; mt < 2; mt++) {
                uint32_t addr = abase + SW128((uint32_t)((rowA + mt * 16) * 128 + kt * 32 + kbA));
                asm volatile("ldmatrix.sync.aligned.m8n8.x4.shared.b16 {%0,%1,%2,%3}, [%4];"
                             : "=r"(a[mt][0]), "=r"(a[mt][1]), "=r"(a[mt][2]), "=r"(a[mt][3])
                             : "r"(addr));
            }
            uint32_t bf[4][4];
            #pragma unroll
            for (int ng = 0; ng < 4; ng++) {
                uint32_t addr = bbase + SW128((uint32_t)((rowB + ng * 16) * 128 + kt * 32 + kbB));
                asm volatile("ldmatrix.sync.aligned.m8n8.x4.shared.b16 {%0,%1,%2,%3}, [%4];"
                             : "=r"(bf[ng][0]), "=r"(bf[ng][1]), "=r"(bf[ng][2]), "=r"(bf[ng][3])
                             : "r"(addr));
            }
            #pragma unroll
            for (int mt = 0; mt < 2; mt++)
                #pragma unroll
                for (int j = 0; j < 8; j++) {
                    uint32_t b0 = bf[j >> 1][(j & 1) * 2];
                    uint32_t b1 = bf[j >> 1][(j & 1) * 2 + 1];
                    asm volatile(
                        "mma.sync.aligned.m16n8k16.row.col.f32.bf16.bf16.f32 "
                        "{%0,%1,%2,%3}, {%4,%5,%6,%7}, {%8,%9}, {%0,%1,%2,%3};"
                        : "+f"(c[mt][j][0]), "+f"(c[mt][j][1]),
                          "+f"(c[mt][j][2]), "+f"(c[mt][j][3])
                        : "r"(a[mt][0]), "r"(a[mt][1]), "r"(a[mt][2]), "r"(a[mt][3]),
                          "r"(b0), "r"(b1));
                }
        }
        __syncthreads();
    }

    float* S = (float*)sm + wid * (32 * 65);
    int g = lane >> 2, t4 = lane & 3;
    #pragma unroll
    for (int mt = 0; mt < 2; mt++)
        #pragma unroll
        for (int j = 0; j < 8; j++) {
            int rr = mt * 16 + g, cc = j * 8 + t4 * 2;
            S[rr * 65 + cc]           = c[mt][j][0];
            S[rr * 65 + cc + 1]       = c[mt][j][1];
            S[(rr + 8) * 65 + cc]     = c[mt][j][2];
            S[(rr + 8) * 65 + cc + 1] = c[mt][j][3];
        }
    __syncwarp();

    const float* sqb = g_sq + (b << 10);
    uint32_t* dbase = g_d2 + ((size_t)b << 20);
    int mg = m0 + wm * 32, ng = n0 + wn * 64;

    float sqc0 = sqb[ng + 2 * lane];
    float sqc1 = sqb[ng + 2 * lane + 1];
    #pragma unroll 4
    for (int r = 0; r < 32; r++) {
        float sq_m = sqb[mg + r];
        uint32_t* drow = dbase + (size_t)(mg + r) * NPTS + ng;
        uint2 v;
        v.x = fkey(sq_m + sqc0 - 2.0f * S[r * 65 + 2 * lane]);
        v.y = fkey(sq_m + sqc1 - 2.0f * S[r * 65 + 2 * lane + 1]);
        *(uint2*)(drow + 2 * lane) = v;
    }

    if (ti != tj) {
        float sq_ml = sqb[mg + lane];
        #pragma unroll 4
        for (int cix = 0; cix < 64; cix++) {
            float sq_n = sqb[ng + cix];
            dbase[(size_t)(ng + cix) * NPTS + mg + lane] =
                fkey(sq_n + sq_ml - 2.0f * S[lane * 65 + cix]);
        }
    }
}

// ---------------------------------------------------------------------------
// Kernel D: selection — coalesced loads (round-12 layout), 32-bit bitonic
// sort, exact rank->index recovery with explicit min-m tie handling.
// ---------------------------------------------------------------------------
__global__ void __launch_bounds__(256, 4) select_knn_kernel(
        const int* __restrict__ layer_idx, float* __restrict__ out, int half) {
    __shared__ uint32_t kbuf[8][64];
    __shared__ uint16_t mbuf[8][64];

    int blk = gridDim.x - 1 - blockIdx.x;          // reversed scheduling
    int warp = blk * 8 + (threadIdx.x >> 5);
    int lane = threadIdx.x & 31;
    int w = (threadIdx.x >> 5);
    if (warp >= NQ) return;

    int li = layer_idx[0];
    int dil = li / 4 + 1;
    if (dil > 3) dil = 3;
    if (dil < 1) dil = 1;

    const uint32_t* row = g_d2 + ((size_t)warp << 10);

    // coalesced: slot s=i*4+j -> m = i*128 + lane*4 + j
    uint32_t u[32];
    #pragma unroll
    for (int i = 0; i < 8; i++) {
        uint4 t = ((const uint4*)row)[i * 32 + lane];
        u[i * 4 + 0] = t.x; u[i * 4 + 1] = t.y;
        u[i * 4 + 2] = t.z; u[i * 4 + 3] = t.w;
    }

    uint32_t lmin = u[0];
    #pragma unroll
    for (int s = 1; s < 32; s++) lmin = min(lmin, u[s]);

    uint32_t sv = lmin;
    #pragma unroll
    for (int k = 2; k <= 32; k <<= 1) {
        #pragma unroll
        for (int j = k >> 1; j > 0; j >>= 1) {
            uint32_t o = __shfl_xor_sync(FULL, sv, j);
            bool up = ((lane & k) == 0) || (k == 32);
            bool lower = ((lane & j) == 0);
            uint32_t mn = min(sv, o), mx = max(sv, o);
            sv = (up == lower) ? mn : mx;
        }
    }
    uint32_t T = __shfl_sync(FULL, sv, 24);

    int cnt = 0;
    #pragma unroll
    for (int s = 0; s < 32; s++) cnt += (u[s] <= T);
    int inc = cnt;
    #pragma unroll
    for (int j = 1; j < 32; j <<= 1) {
        int n = __shfl_up_sync(FULL, inc, j);
        if (lane >= j) inc += n;
    }
    int excl = inc - cnt;
    int C = __shfl_sync(FULL, inc, 31);

    int b = warp >> 10;
    int outbase = warp * KOUT;

    if (C <= 64) {
        int pos = excl;
        #pragma unroll
        for (int s = 0; s < 32; s++) {
            if (u[s] <= T) {
                kbuf[w][pos] = u[s];
                mbuf[w][pos] = (uint16_t)(((s >> 2) << 7) + (lane << 2) + (s & 3));
                pos++;
            }
        }
        __syncwarp();

        uint32_t y0 = (lane < C)      ? kbuf[w][lane]      : 0xFFFFFFFFu;
        uint32_t y1 = (lane + 32 < C) ? kbuf[w][lane + 32] : 0xFFFFFFFFu;
        uint32_t x0 = y0, x1 = y1;

        // bitonic sort of 64 keys (32-bit)
        #pragma unroll
        for (int k = 2; k <= 64; k <<= 1) {
            #pragma unroll
            for (int j = k >> 1; j > 0; j >>= 1) {
                if (j == 32) {
                    uint32_t mn = min(x0, x1), mx = max(x0, x1);
                    x0 = mn; x1 = mx;
                } else {
                    bool lower = ((lane & j) == 0);
                    bool up0, up1;
                    if (k == 64)      { up0 = true;  up1 = true;  }
                    else if (k == 32) { up0 = true;  up1 = false; }
                    else { up0 = up1 = ((lane & k) == 0); }
                    uint32_t o0 = __shfl_xor_sync(FULL, x0, j);
                    uint32_t o1 = __shfl_xor_sync(FULL, x1, j);
                    x0 = (up0 == lower) ? min(x0, o0) : max(x0, o0);
                    x1 = (up1 == lower) ? min(x1, o1) : max(x1, o1);
                }
            }
        }

        // exact rank -> index recovery; ties resolved to ascending m by
        // explicit (tlt+1)-th smallest-m selection over match masks.
        for (int t = 0; t <= 8; t++) {
            int rank = t * dil;
            uint32_t K = __shfl_sync(FULL, x0, rank);
            uint32_t eqs = __ballot_sync(FULL, x0 == K);
            int tlt = __popc(eqs & ((rank > 0) ? ((1u << rank) - 1u) : 0u));
            uint32_t b0m = __ballot_sync(FULL, y0 == K);
            uint32_t b1m = __ballot_sync(FULL, y1 == K);
            if (lane == 0) {
                int m;
                if (tlt == 0 && __popc(b0m) + __popc(b1m) == 1) {
                    // common path: unique match
                    int p2 = b0m ? (__ffs(b0m) - 1) : (32 + __ffs(b1m) - 1);
                    m = (int)mbuf[w][p2];
                } else {
                    // ties: (tlt+1)-th smallest m among matches
                    int prev = -1;
                    for (int q = 0; q <= tlt; q++) {
                        int cur = 0x7FFFFFFF;
                        uint32_t mm = b0m;
                        while (mm) {
                            int p2 = __ffs(mm) - 1; mm &= mm - 1;
                            int mv = (int)mbuf[w][p2];
                            if (mv > prev && mv < cur) cur = mv;
                        }
                        mm = b1m;
                        while (mm) {
                            int p2 = __ffs(mm) - 1; mm &= mm - 1;
                            int mv = (int)mbuf[w][32 + p2];
                            if (mv > prev && mv < cur) cur = mv;
                        }
                        prev = cur;
                    }
                    m = prev;
                }
                int oi = outbase + t;
                out[oi] = (float)((b << 10) + m);
                out[half + oi] = (float)warp;
            }
        }
    } else {
        // rare fallback: exact extract-min on (key, m) — round-12 validated
        uint32_t bv = u[0];
        int bs = 0;
        #pragma unroll
        for (int s = 1; s < 32; s++)
            if (u[s] < bv) { bv = u[s]; bs = s; }

        int iters = 8 * dil + 1;
        for (int r = 0; r < iters; r++) {
            uint32_t wv = bv;
            int wmm = ((bs >> 2) << 7) + (lane << 2) + (bs & 3);
            #pragma unroll
            for (int o = 16; o > 0; o >>= 1) {
                uint32_t ov = __shfl_xor_sync(FULL, wv, o);
                int om = __shfl_xor_sync(FULL, wmm, o);
                if (ov < wv || (ov == wv && om < wmm)) { wv = ov; wmm = om; }
            }
            if ((r % dil) == 0 && lane == 0) {
                int oi = outbase + r / dil;
                out[oi] = (float)((b << 10) + wmm);
                out[half + oi] = (float)warp;
            }
            int owner = (wmm >> 2) & 31;
            if (lane == owner) {
                int s = ((wmm >> 7) << 2) + (wmm & 3);
                #pragma unroll
                for (int ss = 0; ss < 32; ss++)
                    if (ss == s) u[ss] = 0xFFFFFFFFu;
                bv = u[0]; bs = 0;
                #pragma unroll
                for (int ss = 1; ss < 32; ss++)
                    if (u[ss] < bv) { bv = u[ss]; bs = ss; }
            }
        }
    }
}

// ---------------------------------------------------------------------------
// Launch — inputs identified BY SIZE (x = 16,777,216 elems; layer_idx = 1)
// ---------------------------------------------------------------------------
extern "C" void kernel_launch(void* const* d_in, const int* in_sizes, int n_in,
                              void* d_out, int out_size) {
    int xi = 0, li = 1;
    if (n_in >= 2) {
        if (in_sizes[0] >= in_sizes[1]) { xi = 0; li = 1; }
        else                            { xi = 1; li = 0; }
    } else { xi = 0; li = 0; }

    const float* x = (const float*)d_in[xi];
    const int* layer_idx = (const int*)d_in[li];
    float* out = (float*)d_out;
    int half = out_size / 2;

    cudaFuncSetAttribute(gemm_mma_kernel,
                         cudaFuncAttributeMaxDynamicSharedMemorySize, DYN_SMEM);

    dim3 pg(32, 8, 64);
    prep_kernel<<<pg, dim3(32, 8)>>>(x);

    sqreduce_kernel<<<NQ / 256, 256>>>();

    dim3 gg(36, BATCH);
    gemm_mma_kernel<<<gg, 256, DYN_SMEM>>>();

    select_knn_kernel<<<NQ / 8, 256>>>(layer_idx, out, half);
}